// round 6
// baseline (speedup 1.0000x reference)
#include <cuda_runtime.h>
#include <cuda_bf16.h>

// SRU PROJ forward:
//   g1  = sigmoid(u1 + bias)
//   cur = (cur - u0) * g1 + u0
// u: [L, B, D, 2] f32, bias: [D], init: [B, D]
// out: c: [L, B, D] (+ last: [B, D] appended if out_size allows).
//
// One thread per (b, d) column; serial over L.
// R5 change: rolling circular register pipeline, depth 32. Each step consumes
// buf[i] and immediately issues the load for timestep l+DEPTH into the same
// slot -> a constant ~32 loads/thread in flight (≈56 KB/SM outstanding, vs
// ~16/thread for the ping-pong version which also drained at batch
// boundaries). Chip is DRAM-request-parallelism bound; this is the 1.5-2x
// MLP boost the 68%-of-HBM measurement calls for.

#define DEPTH 32

__global__ __launch_bounds__(64, 4)
void sru_fwd_kernel(const float2* __restrict__ u,
                    const float*  __restrict__ bias,
                    const float*  __restrict__ init,
                    float*        __restrict__ c,
                    float*        __restrict__ last,
                    int L, int BD, int D)
{
    const int idx = blockIdx.x * blockDim.x + threadIdx.x;
    if (idx >= BD) return;

    const float bb = __ldg(&bias[idx % D]);
    float cur = init[idx];

    const float2* up = u + idx;   // stride BD float2 per timestep
    float*        cp = c + idx;   // stride BD floats per timestep

    float2 buf[DEPTH];

    // Prologue: fill the pipeline.
    #pragma unroll
    for (int i = 0; i < DEPTH; ++i)
        buf[i] = (i < L) ? __ldcs(&up[i * BD]) : make_float2(0.f, 0.f);

    // Main loop: fully unrolled DEPTH-step body; constant buffer indices keep
    // buf in registers. Consume buf[i], refill slot with load DEPTH ahead.
    int base = 0;
    for (; base + 2 * DEPTH <= L; base += DEPTH) {
        #pragma unroll
        for (int i = 0; i < DEPTH; ++i) {
            const float2 v = buf[i];
            buf[i] = __ldcs(&up[(base + DEPTH + i) * BD]);   // prefetch ahead
            const float g = __fdividef(1.0f, 1.0f + __expf(-(v.y + bb)));
            cur = fmaf(cur - v.x, g, v.x);
            __stcs(&cp[(base + i) * BD], cur);
        }
    }

    // Epilogue: drain the pipeline (last DEPTH elements already in buf).
    #pragma unroll
    for (int i = 0; i < DEPTH; ++i) {
        const int l = base + i;
        if (l < L) {
            const float2 v = buf[i];
            const float g = __fdividef(1.0f, 1.0f + __expf(-(v.y + bb)));
            cur = fmaf(cur - v.x, g, v.x);
            __stcs(&cp[l * BD], cur);
        }
    }
    // Generic tail (only if L not a multiple of DEPTH).
    for (int l = base + DEPTH; l < L; ++l) {
        const float2 v = __ldcs(&up[l * BD]);
        const float g = __fdividef(1.0f, 1.0f + __expf(-(v.y + bb)));
        cur = fmaf(cur - v.x, g, v.x);
        __stcs(&cp[l * BD], cur);
    }

    if (last) last[idx] = cur;
}

extern "C" void kernel_launch(void* const* d_in, const int* in_sizes, int n_in,
                              void* d_out, int out_size)
{
    const float2* u    = (const float2*)d_in[0];
    const float*  bias = (const float*) d_in[1];
    const float*  init = (const float*) d_in[2];

    const int D  = in_sizes[1];            // 1024
    const int BD = in_sizes[2];            // B * D = 32768
    const int L  = in_sizes[0] / (BD * 2); // 1024

    float* c = (float*)d_out;
    float* last = nullptr;
    const long long c_elems = (long long)L * (long long)BD;
    if ((long long)out_size >= c_elems + BD) {
        last = c + c_elems;
    }

    const int threads = 64;
    const int blocks  = (BD + threads - 1) / threads;   // 512
    sru_fwd_kernel<<<blocks, threads>>>(u, bias, init, c, last, L, BD, D);
}